// round 4
// baseline (speedup 1.0000x reference)
#include <cuda_runtime.h>
#include <cuda_bf16.h>
#include <cstdint>
#include <cstddef>

// ---------------------------------------------------------------------------
// Word2vec NCE forward, HMMA bf16, occupancy-2 edition.
//   out[0 .. BATCH*EMB) = embeddings[inputs]   (f32, exact gather)
//   out[BATCH*EMB]      = nce_cost
//
// vs round 3: TB 128->64, threads 512->256, B tile streamed from L2 in 32 KB
// k-chunks via cp.async double buffer => smem ~97 KB, regs 128/thr
// => 2 CTAs/SM, memory phases of one CTA overlap compute of the other.
// ---------------------------------------------------------------------------

namespace {
constexpr int VOCAB = 100000;
constexpr int EMB   = 256;
constexpr int NS    = 256;
constexpr int BATCH = 16384;
constexpr int TB    = 64;                // batch rows per block
constexpr int NBLK  = BATCH / TB;        // 256 blocks
constexpr int NTHR  = 256;               // 8 warps

// smem byte map
constexpr int SM_A    = 0;               // A: 64 x 256 bf16 = 32 KB (swizzled, 512B pitch)
constexpr int SM_B    = 32768;           // B bufs: 2 x (256 x 64 bf16) = 64 KB (128B pitch)
constexpr int SM_BBUF = 32768;           // per-buffer bytes
constexpr int SM_SOFF = 98304;           // soff[256] f32 = 1 KB
constexpr int SM_WSUM = 99328;           // 8 warp partials
constexpr int SM_TOT  = 99328 + 64;
}

__device__ __nv_bfloat16 g_wtb[NS * EMB];   // sampled weights, [s][k] bf16
__device__ float    g_acc;
__device__ unsigned g_done;

// ---------------------------------------------------------------------------
__device__ __forceinline__ long long load_id(const void* p, int i, int is64) {
    return is64 ? ((const long long*)p)[i] : (long long)((const int*)p)[i];
}
__device__ __forceinline__ int detect_is64(const void* p) {
    const int* q = (const int*)p;
    int z = 0;
    #pragma unroll
    for (int i = 0; i < 16; i++) z |= q[2 * i + 1];
    return (z == 0) ? 1 : 0;
}
__device__ __forceinline__ uint32_t smem_u32(const void* p) {
    uint32_t a;
    asm("{ .reg .u64 t; cvta.to.shared.u64 t, %1; cvt.u32.u64 %0, t; }"
        : "=r"(a) : "l"(p));
    return a;
}
// A tile: [row][256 bf16], 512 B pitch, 16B chunks XOR-swizzled by row&7
__device__ __forceinline__ uint32_t a_sw(int row, int chunk) {
    return (uint32_t)row * 512u + (uint32_t)((chunk ^ (row & 7)) << 4);
}
// B buffer: [s][64 bf16], 128 B pitch, 8 chunks of 16B XOR-swizzled by s&7
__device__ __forceinline__ uint32_t b_sw(int s, int chunk) {
    return (uint32_t)s * 128u + (uint32_t)((chunk ^ (s & 7)) << 4);
}

__device__ __forceinline__ void ldsm_x4(uint32_t addr, uint32_t* r) {
    asm volatile("ldmatrix.sync.aligned.m8n8.x4.shared.b16 {%0,%1,%2,%3}, [%4];"
        : "=r"(r[0]), "=r"(r[1]), "=r"(r[2]), "=r"(r[3]) : "r"(addr));
}
__device__ __forceinline__ void ldsm_x2(uint32_t addr, uint32_t* r) {
    asm volatile("ldmatrix.sync.aligned.m8n8.x2.shared.b16 {%0,%1}, [%2];"
        : "=r"(r[0]), "=r"(r[1]) : "r"(addr));
}
__device__ __forceinline__ void mma_bf16(float* c, const uint32_t* a,
                                         const uint32_t* b) {
    asm volatile(
        "mma.sync.aligned.m16n8k16.row.col.f32.bf16.bf16.f32 "
        "{%0,%1,%2,%3}, {%4,%5,%6,%7}, {%8,%9}, {%0,%1,%2,%3};"
        : "+f"(c[0]), "+f"(c[1]), "+f"(c[2]), "+f"(c[3])
        : "r"(a[0]), "r"(a[1]), "r"(a[2]), "r"(a[3]), "r"(b[0]), "r"(b[1]));
}
__device__ __forceinline__ void cp16(uint32_t dst, const void* src) {
    asm volatile("cp.async.cg.shared.global [%0], [%1], 16;"
                 :: "r"(dst), "l"(src) : "memory");
}
__device__ __forceinline__ void cp_commit() {
    asm volatile("cp.async.commit_group;" ::: "memory");
}
__device__ __forceinline__ void cp_wait1() {
    asm volatile("cp.async.wait_group 1;" ::: "memory");
}
__device__ __forceinline__ void cp_wait0() {
    asm volatile("cp.async.wait_group 0;" ::: "memory");
}
__device__ __forceinline__ float softplus_neg(float ax) {
    return __logf(1.0f + __expf(-ax));   // log1p(exp(-ax)), ax >= 0
}

// ---------------------------------------------------------------------------
__global__ void prep_wt_kernel(const float* __restrict__ ncw,
                               const void* __restrict__ sids) {
    __shared__ int s_is64;
    if (threadIdx.x == 0) {
        s_is64 = detect_is64(sids);
        if (blockIdx.x == 0) { g_acc = 0.0f; g_done = 0u; }
    }
    __syncthreads();
    int t = blockIdx.x * blockDim.x + threadIdx.x;   // 0 .. NS*EMB-1
    int s = t >> 8, k = t & 255;
    long long id = load_id(sids, s, s_is64);
    g_wtb[s * EMB + k] = __float2bfloat16(ncw[(size_t)id * EMB + k]);
}

// ---------------------------------------------------------------------------
__global__ void __launch_bounds__(NTHR, 2)
main_kernel(const float* __restrict__ emb, const float* __restrict__ ncw,
            const float* __restrict__ ncb, const void* __restrict__ inputs,
            const void* __restrict__ labels, const void* __restrict__ sids,
            float* __restrict__ out)
{
    extern __shared__ __align__(1024) char smem[];
    const uint32_t smb = smem_u32(smem);
    const int tid  = threadIdx.x;
    const int wid  = tid >> 5;
    const int lane = tid & 31;
    const int b0   = blockIdx.x * TB;
    const int is64 = detect_is64(inputs);
    const float INVL = 1.0f / logf((float)VOCAB + 1.0f);

    const char* wtb = (const char*)g_wtb;

    // ---- kick off B chunks 0 and 1 via cp.async (overlaps everything below)
    // chunk kc covers k in [kc*64, kc*64+64) for all 256 s rows: 2048 x 16B
    {
        #pragma unroll
        for (int i = 0; i < 8; i++) {
            int t = tid + i * NTHR;            // 0..2047
            int s = t >> 3, j = t & 7;
            cp16(smb + SM_B + b_sw(s, j), wtb + s * 512 + 0 * 128 + j * 16);
        }
        cp_commit();
        #pragma unroll
        for (int i = 0; i < 8; i++) {
            int t = tid + i * NTHR;
            int s = t >> 3, j = t & 7;
            cp16(smb + SM_B + SM_BBUF + b_sw(s, j), wtb + s * 512 + 1 * 128 + j * 16);
        }
        cp_commit();
    }

    // ---- sampled-logit offsets: biases[s] - log(NS * prob(s))
    {
        long long id = load_id(sids, tid, is64);
        float fid = (float)id;
        float p = (logf(fid + 2.0f) - logf(fid + 1.0f)) * INVL;
        ((float*)(smem + SM_SOFF))[tid] = ncb[id] - logf((float)NS * p);
    }

    // ---- A tile: gather embed rows -> out (f32) + smem (bf16 swizzled)
    {
        int r    = tid >> 2;                      // 4 threads per row
        int part = tid & 3;                       // 64 k each
        long long g = load_id(inputs, b0 + r, is64);
        const float4* src = (const float4*)emb + (size_t)g * 64 + part * 16;
        float4*       dst = (float4*)out + (size_t)(b0 + r) * 64 + part * 16;
        #pragma unroll
        for (int i = 0; i < 16; i++) {
            float4 v = src[i];
            dst[i] = v;
            __nv_bfloat162 lo = __floats2bfloat162_rn(v.x, v.y);
            __nv_bfloat162 hi = __floats2bfloat162_rn(v.z, v.w);
            uint2 u;
            u.x = *(uint32_t*)&lo;
            u.y = *(uint32_t*)&hi;
            int k0 = part * 64 + i * 4;
            *(uint2*)(smem + SM_A + a_sw(r, k0 >> 3) + ((k0 & 7) << 1)) = u;
        }
    }
    __syncwarp();

    // ---- true-logit xent: warp wid owns rows wid*8 .. +7 (own warp's rows,
    //      so __syncwarp suffices). Prefetch 4 rows per group for MLP.
    float tsum = 0.0f;
    {
        const float4* ncw4 = (const float4*)ncw;
        #pragma unroll
        for (int g = 0; g < 2; g++) {
            long long labs[4];
            float4 w0[4], w1[4];
            #pragma unroll
            for (int rr = 0; rr < 4; rr++) {
                int r = wid * 8 + g * 4 + rr;
                labs[rr] = load_id(labels, b0 + r, is64);
                w0[rr] = ncw4[(size_t)labs[rr] * 64 + lane * 2];
                w1[rr] = ncw4[(size_t)labs[rr] * 64 + lane * 2 + 1];
            }
            #pragma unroll
            for (int rr = 0; rr < 4; rr++) {
                int r = wid * 8 + g * 4 + rr;
                uint4 eu = *(const uint4*)(smem + SM_A + a_sw(r, lane));
                float2 e0 = __bfloat1622float2(*(__nv_bfloat162*)&eu.x);
                float2 e1 = __bfloat1622float2(*(__nv_bfloat162*)&eu.y);
                float2 e2 = __bfloat1622float2(*(__nv_bfloat162*)&eu.z);
                float2 e3 = __bfloat1622float2(*(__nv_bfloat162*)&eu.w);
                float d = e0.x * w0[rr].x;
                d = fmaf(e0.y, w0[rr].y, d); d = fmaf(e1.x, w0[rr].z, d);
                d = fmaf(e1.y, w0[rr].w, d); d = fmaf(e2.x, w1[rr].x, d);
                d = fmaf(e2.y, w1[rr].y, d); d = fmaf(e3.x, w1[rr].z, d);
                d = fmaf(e3.y, w1[rr].w, d);
                #pragma unroll
                for (int o = 16; o > 0; o >>= 1)
                    d += __shfl_xor_sync(0xffffffffu, d, o);
                if (lane == 0) {
                    float fl = (float)labs[rr];
                    float p  = (logf(fl + 2.0f) - logf(fl + 1.0f)) * INVL;
                    float tl = d + ncb[labs[rr]] - logf((float)NS * p);
                    tsum += fmaxf(tl, 0.0f) - tl + softplus_neg(fabsf(tl));
                }
            }
        }
    }
    __syncthreads();                 // A tile + soff visible to all warps

    // ---- HMMA GEMM: 64x256x256; warp grid 2m x 4n, warp tile 32x64
    const int wm = wid & 1;
    const int wn = wid >> 1;
    float acc[2][8][4];
    #pragma unroll
    for (int mt = 0; mt < 2; mt++)
        #pragma unroll
        for (int nt = 0; nt < 8; nt++)
            #pragma unroll
            for (int j = 0; j < 4; j++) acc[mt][nt][j] = 0.0f;

    const int amat  = lane >> 3;                        // 0..3
    const int arow0 = wm * 32 + ((amat & 1) << 3) + (lane & 7);
    const int arow1 = arow0 + 16;
    const int aext  = amat >> 1;                        // k16-chunk +0/+1
    const uint32_t abase0 = smb + SM_A + (uint32_t)arow0 * 512u;
    const uint32_t abase1 = smb + SM_A + (uint32_t)arow1 * 512u;
    const int axor0 = arow0 & 7, axor1 = arow1 & 7;

    const int li    = lane & 15;
    const int bhalf = li >> 3;                          // k16-chunk +0/+1
    const int brow  = wn * 64 + (li & 7);               // +8*nt
    const int bxor  = brow & 7;

    #pragma unroll
    for (int kc = 0; kc < 4; kc++) {
        cp_wait1();                   // chunk kc landed
        __syncthreads();
        const uint32_t bbuf = smb + SM_B + (uint32_t)(kc & 1) * SM_BBUF;
        #pragma unroll
        for (int ksl = 0; ksl < 4; ksl++) {
            const int ks = kc * 4 + ksl;
            uint32_t a0[4], a1[4];
            int ac = ks * 2 + aext;
            ldsm_x4(abase0 + (uint32_t)(((ac ^ axor0) & 31) << 4), a0);
            ldsm_x4(abase1 + (uint32_t)(((ac ^ axor1) & 31) << 4), a1);
            int bc = ksl * 2 + bhalf;
            #pragma unroll
            for (int nt = 0; nt < 8; nt++) {
                uint32_t b[2];
                int r = brow + nt * 8;
                uint32_t boff = (uint32_t)r * 128u
                              + (uint32_t)(((bc ^ bxor) & 7) << 4);
                ldsm_x2(bbuf + boff, b);
                mma_bf16(acc[0][nt], a0, b);
                mma_bf16(acc[1][nt], a1, b);
            }
        }
        __syncthreads();              // buffer fully consumed by all warps
        if (kc < 2) {                 // refill this buffer with chunk kc+2
            #pragma unroll
            for (int i = 0; i < 8; i++) {
                int t = tid + i * NTHR;
                int s = t >> 3, j = t & 7;
                cp16(bbuf + b_sw(s, j), wtb + s * 512 + (kc + 2) * 128 + j * 16);
            }
        }
        cp_commit();                  // keep group count in lockstep
    }
    cp_wait0();

    // ---- softplus epilogue on c-frags
    const float* soff = (const float*)(smem + SM_SOFF);
    float ssum = 0.0f;
    {
        const int colb = wn * 64 + ((lane & 3) << 1);
        #pragma unroll
        for (int nt = 0; nt < 8; nt++) {
            float s0 = soff[colb + nt * 8];
            float s1 = soff[colb + nt * 8 + 1];
            #pragma unroll
            for (int mt = 0; mt < 2; mt++) {
                float l0 = acc[mt][nt][0] + s0;
                float l1 = acc[mt][nt][1] + s1;
                float l2 = acc[mt][nt][2] + s0;
                float l3 = acc[mt][nt][3] + s1;
                ssum += fmaxf(l0, 0.0f) + softplus_neg(fabsf(l0));
                ssum += fmaxf(l1, 0.0f) + softplus_neg(fabsf(l1));
                ssum += fmaxf(l2, 0.0f) + softplus_neg(fabsf(l2));
                ssum += fmaxf(l3, 0.0f) + softplus_neg(fabsf(l3));
            }
        }
    }

    // ---- reduce: warp -> block -> global
    float wsum = ssum + tsum;
    #pragma unroll
    for (int o = 16; o > 0; o >>= 1) wsum += __shfl_xor_sync(0xffffffffu, wsum, o);
    if (lane == 0) ((float*)(smem + SM_WSUM))[wid] = wsum;
    __syncthreads();

    if (tid == 0) {
        float t = 0.0f;
        #pragma unroll
        for (int i = 0; i < 8; i++) t += ((float*)(smem + SM_WSUM))[i];
        atomicAdd(&g_acc, t);
        __threadfence();
        unsigned cnt = atomicAdd(&g_done, 1u);
        if (cnt == (unsigned)(NBLK - 1)) {
            __threadfence();
            out[(size_t)BATCH * EMB] = g_acc * (1.0f / (float)BATCH);
        }
    }
}

// ---------------------------------------------------------------------------
extern "C" void kernel_launch(void* const* d_in, const int* in_sizes, int n_in,
                              void* d_out, int out_size) {
    const float* emb    = (const float*)d_in[0];
    const float* ncw    = (const float*)d_in[1];
    const float* ncb    = (const float*)d_in[2];
    const void*  inputs = d_in[3];
    const void*  labels = d_in[4];
    const void*  sids   = d_in[5];
    float* out = (float*)d_out;

    cudaFuncSetAttribute(main_kernel,
                         cudaFuncAttributeMaxDynamicSharedMemorySize, SM_TOT);

    prep_wt_kernel<<<(NS * EMB) / 1024, 1024>>>(ncw, sids);
    main_kernel<<<NBLK, NTHR, SM_TOT>>>(emb, ncw, ncb, inputs, labels, sids, out);
}